// round 1
// baseline (speedup 1.0000x reference)
#include <cuda_runtime.h>
#include <math.h>
#include <stdint.h>

#define NN 10000
#define EE 160000
#define CC 64
#define RR 32
#define NPB 16
constexpr float CUTOFF_F = 5.0f;
constexpr float PI_OVER_CUT = 0.62831853071795864769f; // pi/5

// Scratch (device globals; no runtime allocation allowed)
__device__ float g_Xn[(size_t)NN * CC * 9];        // normalized node tensors
__device__ float g_comp[(size_t)NN * CC * 12];     // mixed I/A/S compact: {ic,a0,a1,a2,s00,s01,s02,s11,s12,s22,pad,pad}
__device__ float g_msg[(size_t)NN * CC * 12];      // accumulated messages, same layout

__device__ __forceinline__ float silu_f(float x) { return x / (1.0f + __expf(-x)); }

__device__ __forceinline__ void red4(float* p, float a, float b, float c, float d) {
    asm volatile("red.global.add.v4.f32 [%0], {%1,%2,%3,%4};"
                 :: "l"(p), "f"(a), "f"(b), "f"(c), "f"(d) : "memory");
}
__device__ __forceinline__ void red2(float* p, float a, float b) {
    asm volatile("red.global.add.v2.f32 [%0], {%1,%2};"
                 :: "l"(p), "f"(a), "f"(b) : "memory");
}

// Build full 3x3 from compact comps
__device__ __forceinline__ void build_mat(float M[3][3], float ic, float a0, float a1, float a2,
                                          float s00, float s01, float s02, float s11, float s12, float s22) {
    M[0][0] = ic + s00;  M[0][1] = a0 + s01;  M[0][2] = a1 + s02;
    M[1][0] = -a0 + s01; M[1][1] = ic + s11;  M[1][2] = a2 + s12;
    M[2][0] = -a1 + s02; M[2][1] = -a2 + s12; M[2][2] = ic + s22;
}

// ---------------------------------------------------------------- zero msg
__global__ void k_zero() {
    size_t i = (size_t)blockIdx.x * blockDim.x + threadIdx.x;
    const size_t total = (size_t)NN * CC * 12 / 4;
    float4 z = make_float4(0.f, 0.f, 0.f, 0.f);
    for (; i < total; i += (size_t)gridDim.x * blockDim.x)
        reinterpret_cast<float4*>(g_msg)[i] = z;
}

// ---------------------------------------------------------------- node pre
// Per (n,c): Xn = X/(|X|^2+1), decompose; per node: channel-mix with Wt0..2 -> g_comp
__global__ void __launch_bounds__(256) k_node_pre(const float* __restrict__ X,
                                                  const float* __restrict__ Wt) {
    extern __shared__ float sm[];
    float* sW = sm;              // 3*4096 floats (Wt0, Wt1, Wt2)
    float* sc = sW + 3 * 4096;   // NPB*64*10

    int tid = threadIdx.x;
    for (int i = tid; i < 3 * 4096; i += 256) sW[i] = Wt[i];

    int n0 = blockIdx.x * NPB;

    for (int idx = tid; idx < NPB * CC; idx += 256) {
        int ni = idx >> 6, c = idx & 63;
        int n = n0 + ni;
        if (n < NN) {
            const float* xp = X + ((size_t)n * CC + c) * 9;
            float x[9];
#pragma unroll
            for (int i = 0; i < 9; i++) x[i] = __ldg(xp + i);
            float nrm = 0.f;
#pragma unroll
            for (int i = 0; i < 9; i++) nrm += x[i] * x[i];
            float inv = 1.0f / (nrm + 1.0f);
            float xn[9];
#pragma unroll
            for (int i = 0; i < 9; i++) xn[i] = x[i] * inv;
            float* op = g_Xn + ((size_t)n * CC + c) * 9;
#pragma unroll
            for (int i = 0; i < 9; i++) op[i] = xn[i];
            float ic = (xn[0] + xn[4] + xn[8]) * (1.0f / 3.0f);
            float* s = sc + ((size_t)ni * 64 + c) * 10;
            s[0] = ic;
            s[1] = 0.5f * (xn[1] - xn[3]);
            s[2] = 0.5f * (xn[2] - xn[6]);
            s[3] = 0.5f * (xn[5] - xn[7]);
            s[4] = xn[0] - ic;
            s[5] = 0.5f * (xn[1] + xn[3]);
            s[6] = 0.5f * (xn[2] + xn[6]);
            s[7] = xn[4] - ic;
            s[8] = 0.5f * (xn[5] + xn[7]);
            s[9] = xn[8] - ic;
        }
    }
    __syncthreads();

    {
        int ni = tid >> 4, g = tid & 15;
        int l0 = g * 4;
        int n = n0 + ni;
        if (n >= NN) return;
        float aI[4] = {0, 0, 0, 0};
        float aA[3][4] = {};
        float aS[6][4] = {};
#pragma unroll 4
        for (int k = 0; k < 64; k++) {
            const float* s = sc + ((size_t)ni * 64 + k) * 10;
            float c10[10];
#pragma unroll
            for (int q = 0; q < 10; q++) c10[q] = s[q];
            float w0v[4], w1v[4], w2v[4];
            *(float4*)w0v = *(const float4*)&sW[k * 64 + l0];
            *(float4*)w1v = *(const float4*)&sW[4096 + k * 64 + l0];
            *(float4*)w2v = *(const float4*)&sW[8192 + k * 64 + l0];
#pragma unroll
            for (int j = 0; j < 4; j++) {
                aI[j] += c10[0] * w0v[j];
#pragma unroll
                for (int i = 0; i < 3; i++) aA[i][j] += c10[1 + i] * w1v[j];
#pragma unroll
                for (int i = 0; i < 6; i++) aS[i][j] += c10[4 + i] * w2v[j];
            }
        }
#pragma unroll
        for (int j = 0; j < 4; j++) {
            int l = l0 + j;
            float4* q = reinterpret_cast<float4*>(g_comp + ((size_t)n * 64 + l) * 12);
            q[0] = make_float4(aI[j], aA[0][j], aA[1][j], aA[2][j]);
            q[1] = make_float4(aS[0][j], aS[1][j], aS[2][j], aS[3][j]);
            q[2] = make_float4(aS[4][j], aS[5][j], 0.f, 0.f);
        }
    }
}

// ---------------------------------------------------------------- edge kernel
// Persistent: weights in smem; 64-edge tiles; fused 3-layer MLP + gather/scatter.
__global__ void __launch_bounds__(256, 1) k_edge(
    const float* __restrict__ edge_attr, const int* __restrict__ edge_index,
    const float* __restrict__ edge_weight,
    const float* __restrict__ W1, const float* __restrict__ b1,
    const float* __restrict__ W2, const float* __restrict__ b2,
    const float* __restrict__ W3, const float* __restrict__ b3) {
    extern __shared__ float sm[];
    float* sW1 = sm;               // 32*64   = 2048
    float* sW2 = sW1 + 2048;       // 64*128  = 8192
    float* sW3 = sW2 + 8192;       // 128*192 = 24576
    float* sB1 = sW3 + 24576;      // 64
    float* sB2 = sB1 + 64;         // 128
    float* sB3 = sB2 + 128;        // 192
    float* sAt = sB3 + 192;        // 32*64  (edge_attr^T: [k][e])
    float* sH1 = sAt + 2048;       // 64*64  ([j][e])
    float* sH2 = sH1 + 4096;       // 128*64 ([j][e])
    float* sCw = sH2 + 8192;       // 64
    int* sSrc = reinterpret_cast<int*>(sCw + 64);  // 64
    int* sDst = sSrc + 64;                          // 64

    int tid = threadIdx.x;
    for (int i = tid; i < 2048; i += 256) sW1[i] = W1[i];
    for (int i = tid; i < 8192; i += 256) sW2[i] = W2[i];
    for (int i = tid; i < 24576; i += 256) sW3[i] = W3[i];
    if (tid < 64) sB1[tid] = b1[tid];
    if (tid < 128) sB2[tid] = b2[tid];
    if (tid < 192) sB3[tid] = b3[tid];
    __syncthreads();

    const int tx = tid & 15, ty = tid >> 4;
    const int e0 = tx * 4;
    const int nTiles = EE / 64;

    for (int tile = blockIdx.x; tile < nTiles; tile += gridDim.x) {
        int base = tile * 64;
        if (tid < 64) {
            int e = base + tid;
            sSrc[tid] = edge_index[e];
            sDst[tid] = edge_index[EE + e];
            float w = edge_weight[e];
            float cw = 0.5f * (__cosf(w * PI_OVER_CUT) + 1.0f);
            sCw[tid] = (w < CUTOFF_F) ? cw : 0.0f;
        }
        for (int i = tid; i < 512; i += 256) {
            int e = i >> 3, kq = i & 7;
            float4 v = __ldg(reinterpret_cast<const float4*>(edge_attr + ((size_t)(base + e)) * 32 + kq * 4));
            sAt[(kq * 4 + 0) * 64 + e] = v.x;
            sAt[(kq * 4 + 1) * 64 + e] = v.y;
            sAt[(kq * 4 + 2) * 64 + e] = v.z;
            sAt[(kq * 4 + 3) * 64 + e] = v.w;
        }
        __syncthreads();

        // ---- layer 1: [64e,32] @ [32,64] -> sH1[j][e]
        {
            int j0 = ty * 4;
            float acc[4][4];
#pragma unroll
            for (int jj = 0; jj < 4; jj++) {
                float b = sB1[j0 + jj];
#pragma unroll
                for (int ee = 0; ee < 4; ee++) acc[ee][jj] = b;
            }
#pragma unroll 4
            for (int k = 0; k < 32; k++) {
                float av[4], wv[4];
                *(float4*)av = *(const float4*)&sAt[k * 64 + e0];
                *(float4*)wv = *(const float4*)&sW1[k * 64 + j0];
#pragma unroll
                for (int ee = 0; ee < 4; ee++)
#pragma unroll
                    for (int jj = 0; jj < 4; jj++) acc[ee][jj] += av[ee] * wv[jj];
            }
#pragma unroll
            for (int jj = 0; jj < 4; jj++) {
                float4 o = make_float4(silu_f(acc[0][jj]), silu_f(acc[1][jj]),
                                       silu_f(acc[2][jj]), silu_f(acc[3][jj]));
                *(float4*)&sH1[(j0 + jj) * 64 + e0] = o;
            }
        }
        __syncthreads();

        // ---- layer 2: [64e,64] @ [64,128] -> sH2[j][e]
        {
            int j0 = ty * 8;
            float acc[4][8];
#pragma unroll
            for (int jj = 0; jj < 8; jj++) {
                float b = sB2[j0 + jj];
#pragma unroll
                for (int ee = 0; ee < 4; ee++) acc[ee][jj] = b;
            }
#pragma unroll 2
            for (int k = 0; k < 64; k++) {
                float av[4], wv[8];
                *(float4*)av = *(const float4*)&sH1[k * 64 + e0];
                *(float4*)(wv) = *(const float4*)&sW2[k * 128 + j0];
                *(float4*)(wv + 4) = *(const float4*)&sW2[k * 128 + j0 + 4];
#pragma unroll
                for (int ee = 0; ee < 4; ee++)
#pragma unroll
                    for (int jj = 0; jj < 8; jj++) acc[ee][jj] += av[ee] * wv[jj];
            }
#pragma unroll
            for (int jj = 0; jj < 8; jj++) {
                float4 o = make_float4(silu_f(acc[0][jj]), silu_f(acc[1][jj]),
                                       silu_f(acc[2][jj]), silu_f(acc[3][jj]));
                *(float4*)&sH2[(j0 + jj) * 64 + e0] = o;
            }
        }
        __syncthreads();

        // ---- layer 3: [64e,128] @ [128,192] + fused scatter epilogue
        {
            int j0 = ty * 12;  // channels 4*ty .. 4*ty+3
            float acc[4][12];
#pragma unroll
            for (int jj = 0; jj < 12; jj++) {
                float b = sB3[j0 + jj];
#pragma unroll
                for (int ee = 0; ee < 4; ee++) acc[ee][jj] = b;
            }
#pragma unroll 2
            for (int k = 0; k < 128; k++) {
                float av[4], wv[12];
                *(float4*)av = *(const float4*)&sH2[k * 64 + e0];
                *(float4*)(wv) = *(const float4*)&sW3[k * 192 + j0];
                *(float4*)(wv + 4) = *(const float4*)&sW3[k * 192 + j0 + 4];
                *(float4*)(wv + 8) = *(const float4*)&sW3[k * 192 + j0 + 8];
#pragma unroll
                for (int ee = 0; ee < 4; ee++)
#pragma unroll
                    for (int jj = 0; jj < 12; jj++) acc[ee][jj] += av[ee] * wv[jj];
            }
#pragma unroll
            for (int ee = 0; ee < 4; ee++) {
                int e = e0 + ee;
                float cw = sCw[e];
                int s = sSrc[e], d = sDst[e];
#pragma unroll
                for (int cc = 0; cc < 4; cc++) {
                    int c = ty * 4 + cc;
                    float fI = silu_f(acc[ee][cc * 3 + 0]) * cw;
                    float fA = silu_f(acc[ee][cc * 3 + 1]) * cw;
                    float fS = silu_f(acc[ee][cc * 3 + 2]) * cw;
                    const float4* p = reinterpret_cast<const float4*>(g_comp + ((size_t)d * 64 + c) * 12);
                    float4 v0 = __ldg(p), v1 = __ldg(p + 1), v2 = __ldg(p + 2);
                    float* q = g_msg + ((size_t)s * 64 + c) * 12;
                    red4(q, fI * v0.x, fA * v0.y, fA * v0.z, fA * v0.w);
                    red4(q + 4, fS * v1.x, fS * v1.y, fS * v1.z, fS * v1.w);
                    red2(q + 8, fS * v2.x, fS * v2.y);
                }
            }
        }
        __syncthreads();
    }
}

// ---------------------------------------------------------------- node post
__global__ void __launch_bounds__(256) k_node_post(const float* __restrict__ Wt,
                                                   float* __restrict__ out) {
    extern __shared__ float sm[];
    float* sW = sm;              // 3*4096 (Wt3, Wt4, Wt5)
    float* sc = sW + 3 * 4096;   // NPB*64*10

    int tid = threadIdx.x;
    for (int i = tid; i < 3 * 4096; i += 256) sW[i] = Wt[3 * 4096 + i];

    int n0 = blockIdx.x * NPB;

    for (int idx = tid; idx < NPB * CC; idx += 256) {
        int ni = idx >> 6, c = idx & 63;
        int n = n0 + ni;
        if (n < NN) {
            const float4* mp = reinterpret_cast<const float4*>(g_msg + ((size_t)n * 64 + c) * 12);
            float4 m0 = mp[0], m1 = mp[1], m2 = mp[2];
            const float4* yp = reinterpret_cast<const float4*>(g_comp + ((size_t)n * 64 + c) * 12);
            float4 y0 = yp[0], y1 = yp[1], y2 = yp[2];
            float Mg[3][3], Y[3][3];
            build_mat(Mg, m0.x, m0.y, m0.z, m0.w, m1.x, m1.y, m1.z, m1.w, m2.x, m2.y);
            build_mat(Y, y0.x, y0.y, y0.z, y0.w, y1.x, y1.y, y1.z, y1.w, y2.x, y2.y);
            float P[3][3];
#pragma unroll
            for (int i = 0; i < 3; i++)
#pragma unroll
                for (int j = 0; j < 3; j++) {
                    float v = 0.f;
#pragma unroll
                    for (int k = 0; k < 3; k++) v += Mg[i][k] * Y[k][j] + Y[i][k] * Mg[k][j];
                    P[i][j] = v;
                }
            float nrm = 0.f;
#pragma unroll
            for (int i = 0; i < 3; i++)
#pragma unroll
                for (int j = 0; j < 3; j++) nrm += P[i][j] * P[i][j];
            float inv = 1.0f / (nrm + 1.0f);
            float ic = (P[0][0] + P[1][1] + P[2][2]) * (1.0f / 3.0f);
            float* s = sc + ((size_t)ni * 64 + c) * 10;
            s[0] = ic * inv;
            s[1] = 0.5f * (P[0][1] - P[1][0]) * inv;
            s[2] = 0.5f * (P[0][2] - P[2][0]) * inv;
            s[3] = 0.5f * (P[1][2] - P[2][1]) * inv;
            s[4] = (P[0][0] - ic) * inv;
            s[5] = 0.5f * (P[0][1] + P[1][0]) * inv;
            s[6] = 0.5f * (P[0][2] + P[2][0]) * inv;
            s[7] = (P[1][1] - ic) * inv;
            s[8] = 0.5f * (P[1][2] + P[2][1]) * inv;
            s[9] = (P[2][2] - ic) * inv;
        }
    }
    __syncthreads();

    {
        int ni = tid >> 4, g = tid & 15;
        int l0 = g * 4;
        int n = n0 + ni;
        if (n >= NN) return;
        float aI[4] = {0, 0, 0, 0};
        float aA[3][4] = {};
        float aS[6][4] = {};
#pragma unroll 4
        for (int k = 0; k < 64; k++) {
            const float* s = sc + ((size_t)ni * 64 + k) * 10;
            float c10[10];
#pragma unroll
            for (int q = 0; q < 10; q++) c10[q] = s[q];
            float w0v[4], w1v[4], w2v[4];
            *(float4*)w0v = *(const float4*)&sW[k * 64 + l0];
            *(float4*)w1v = *(const float4*)&sW[4096 + k * 64 + l0];
            *(float4*)w2v = *(const float4*)&sW[8192 + k * 64 + l0];
#pragma unroll
            for (int j = 0; j < 4; j++) {
                aI[j] += c10[0] * w0v[j];
#pragma unroll
                for (int i = 0; i < 3; i++) aA[i][j] += c10[1 + i] * w1v[j];
#pragma unroll
                for (int i = 0; i < 6; i++) aS[i][j] += c10[4 + i] * w2v[j];
            }
        }
#pragma unroll
        for (int j = 0; j < 4; j++) {
            int l = l0 + j;
            float D[3][3];
            build_mat(D, aI[j], aA[0][j], aA[1][j], aA[2][j],
                      aS[0][j], aS[1][j], aS[2][j], aS[3][j], aS[4][j], aS[5][j]);
            const float* xp = g_Xn + ((size_t)n * 64 + l) * 9;
            float* op = out + ((size_t)n * 64 + l) * 9;
#pragma unroll
            for (int i = 0; i < 3; i++)
#pragma unroll
                for (int j2 = 0; j2 < 3; j2++) {
                    float dd = 0.f;
#pragma unroll
                    for (int k = 0; k < 3; k++) dd += D[i][k] * D[k][j2];
                    op[i * 3 + j2] = __ldg(xp + i * 3 + j2) + D[i][j2] + dd;
                }
        }
    }
}

// ---------------------------------------------------------------- launch
extern "C" void kernel_launch(void* const* d_in, const int* in_sizes, int n_in,
                              void* d_out, int out_size) {
    const float* X  = (const float*)d_in[0];
    const int*   ei = (const int*)d_in[1];
    const float* ew = (const float*)d_in[2];
    const float* ea = (const float*)d_in[3];
    const float* W1 = (const float*)d_in[4];
    const float* b1 = (const float*)d_in[5];
    const float* W2 = (const float*)d_in[6];
    const float* b2 = (const float*)d_in[7];
    const float* W3 = (const float*)d_in[8];
    const float* b3 = (const float*)d_in[9];
    const float* Wt = (const float*)d_in[10];
    float* out = (float*)d_out;

    const int smNode = (3 * 4096 + NPB * 64 * 10) * 4;                 // ~90 KB
    const int smEdge = (2048 + 8192 + 24576 + 64 + 128 + 192 + 2048 +
                        4096 + 8192 + 64 + 128) * 4;                    // ~194 KB

    cudaFuncSetAttribute(k_node_pre, cudaFuncAttributeMaxDynamicSharedMemorySize, smNode);
    cudaFuncSetAttribute(k_node_post, cudaFuncAttributeMaxDynamicSharedMemorySize, smNode);
    cudaFuncSetAttribute(k_edge, cudaFuncAttributeMaxDynamicSharedMemorySize, smEdge);

    k_zero<<<256, 256>>>();
    k_node_pre<<<(NN + NPB - 1) / NPB, 256, smNode>>>(X, Wt);
    k_edge<<<148, 256, smEdge>>>(ea, ei, ew, W1, b1, W2, b2, W3, b3);
    k_node_post<<<(NN + NPB - 1) / NPB, 256, smNode>>>(Wt, out);
}

// round 2
// speedup vs baseline: 1.0749x; 1.0749x over previous
#include <cuda_runtime.h>
#include <math.h>
#include <stdint.h>

#define NN 10000
#define EE 160000
#define CC 64
#define RR 32
#define NPB 8
constexpr float CUTOFF_F = 5.0f;
constexpr float PI_OVER_CUT = 0.62831853071795864769f; // pi/5

// Scratch (device globals; no runtime allocation allowed)
__device__ float g_Xn[(size_t)NN * CC * 9];        // normalized node tensors
__device__ float g_comp[(size_t)NN * CC * 12];     // mixed I/A/S compact
__device__ float g_msg[(size_t)NN * CC * 12];      // accumulated messages

__device__ __forceinline__ float silu_f(float x) { return x / (1.0f + __expf(-x)); }

__device__ __forceinline__ void red4(float* p, float a, float b, float c, float d) {
    asm volatile("red.global.add.v4.f32 [%0], {%1,%2,%3,%4};"
                 :: "l"(p), "f"(a), "f"(b), "f"(c), "f"(d) : "memory");
}
__device__ __forceinline__ void red2(float* p, float a, float b) {
    asm volatile("red.global.add.v2.f32 [%0], {%1,%2};"
                 :: "l"(p), "f"(a), "f"(b) : "memory");
}

// ---- packed fp32x2 helpers (Blackwell FFMA2) ----
__device__ __forceinline__ unsigned long long pack2(float x) {
    unsigned long long r;
    asm("mov.b64 %0, {%1, %1};" : "=l"(r) : "f"(x));
    return r;
}
__device__ __forceinline__ void ffma2(unsigned long long& d, unsigned long long a, unsigned long long b) {
    asm("fma.rn.f32x2 %0, %1, %2, %0;" : "+l"(d) : "l"(a), "l"(b));
}
__device__ __forceinline__ float2 unp2(unsigned long long v) {
    float2 f;
    asm("mov.b64 {%0, %1}, %2;" : "=f"(f.x), "=f"(f.y) : "l"(v));
    return f;
}

// Build full 3x3 from compact comps
__device__ __forceinline__ void build_mat(float M[3][3], float ic, float a0, float a1, float a2,
                                          float s00, float s01, float s02, float s11, float s12, float s22) {
    M[0][0] = ic + s00;  M[0][1] = a0 + s01;  M[0][2] = a1 + s02;
    M[1][0] = -a0 + s01; M[1][1] = ic + s11;  M[1][2] = a2 + s12;
    M[2][0] = -a1 + s02; M[2][1] = -a2 + s12; M[2][2] = ic + s22;
}

// ---------------------------------------------------------------- zero msg
__global__ void k_zero() {
    size_t i = (size_t)blockIdx.x * blockDim.x + threadIdx.x;
    const size_t total = (size_t)NN * CC * 12 / 4;
    float4 z = make_float4(0.f, 0.f, 0.f, 0.f);
    for (; i < total; i += (size_t)gridDim.x * blockDim.x)
        reinterpret_cast<float4*>(g_msg)[i] = z;
}

// ---------------------------------------------------------------- node pre
// Per (n,c): Xn = X/(|X|^2+1), decompose; channel-mix Wt0..2 -> g_comp
// sc is planar: sc[q * (NPB*64) + ni*64 + c], q in [0,10)
__global__ void __launch_bounds__(256) k_node_pre(const float* __restrict__ X,
                                                  const float* __restrict__ Wt) {
    extern __shared__ float sm[];
    float* sW = sm;              // 3*4096 floats (Wt0, Wt1, Wt2)
    float* sc = sW + 3 * 4096;   // 10 * NPB*64

    const int PL = NPB * 64;
    int tid = threadIdx.x;
    for (int i = tid; i < 3 * 4096; i += 256) sW[i] = Wt[i];

    int n0 = blockIdx.x * NPB;

    for (int idx = tid; idx < NPB * CC; idx += 256) {
        int ni = idx >> 6, c = idx & 63;
        int n = n0 + ni;
        if (n < NN) {
            const float* xp = X + ((size_t)n * CC + c) * 9;
            float x[9];
#pragma unroll
            for (int i = 0; i < 9; i++) x[i] = __ldg(xp + i);
            float nrm = 0.f;
#pragma unroll
            for (int i = 0; i < 9; i++) nrm += x[i] * x[i];
            float inv = 1.0f / (nrm + 1.0f);
            float xn[9];
#pragma unroll
            for (int i = 0; i < 9; i++) xn[i] = x[i] * inv;
            float* op = g_Xn + ((size_t)n * CC + c) * 9;
#pragma unroll
            for (int i = 0; i < 9; i++) op[i] = xn[i];
            float ic = (xn[0] + xn[4] + xn[8]) * (1.0f / 3.0f);
            int o = ni * 64 + c;
            sc[0 * PL + o] = ic;
            sc[1 * PL + o] = 0.5f * (xn[1] - xn[3]);
            sc[2 * PL + o] = 0.5f * (xn[2] - xn[6]);
            sc[3 * PL + o] = 0.5f * (xn[5] - xn[7]);
            sc[4 * PL + o] = xn[0] - ic;
            sc[5 * PL + o] = 0.5f * (xn[1] + xn[3]);
            sc[6 * PL + o] = 0.5f * (xn[2] + xn[6]);
            sc[7 * PL + o] = xn[4] - ic;
            sc[8 * PL + o] = 0.5f * (xn[5] + xn[7]);
            sc[9 * PL + o] = xn[8] - ic;
        }
    }
    __syncthreads();

    {
        int ni = tid >> 5, g = tid & 31;
        int j0 = g * 2;
        int n = n0 + ni;
        if (n >= NN) return;
        float aI[2] = {0, 0};
        float aA[3][2] = {};
        float aS[6][2] = {};
        const float* scb = sc + ni * 64;
#pragma unroll 4
        for (int k = 0; k < 64; k++) {
            float c10[10];
#pragma unroll
            for (int q = 0; q < 10; q++) c10[q] = scb[q * PL + k];
            float2 w0 = *(const float2*)&sW[k * 64 + j0];
            float2 w1 = *(const float2*)&sW[4096 + k * 64 + j0];
            float2 w2 = *(const float2*)&sW[8192 + k * 64 + j0];
            aI[0] += c10[0] * w0.x; aI[1] += c10[0] * w0.y;
#pragma unroll
            for (int i = 0; i < 3; i++) { aA[i][0] += c10[1 + i] * w1.x; aA[i][1] += c10[1 + i] * w1.y; }
#pragma unroll
            for (int i = 0; i < 6; i++) { aS[i][0] += c10[4 + i] * w2.x; aS[i][1] += c10[4 + i] * w2.y; }
        }
#pragma unroll
        for (int j = 0; j < 2; j++) {
            int l = j0 + j;
            float4* q = reinterpret_cast<float4*>(g_comp + ((size_t)n * 64 + l) * 12);
            q[0] = make_float4(aI[j], aA[0][j], aA[1][j], aA[2][j]);
            q[1] = make_float4(aS[0][j], aS[1][j], aS[2][j], aS[3][j]);
            q[2] = make_float4(aS[4][j], aS[5][j], 0.f, 0.f);
        }
    }
}

// ---------------------------------------------------------------- edge kernel
// Persistent: weights in smem; 64-edge tiles; fused 3-layer MLP (FFMA2) + gather/scatter.
__global__ void __launch_bounds__(256, 1) k_edge(
    const float* __restrict__ edge_attr, const int* __restrict__ edge_index,
    const float* __restrict__ edge_weight,
    const float* __restrict__ W1, const float* __restrict__ b1,
    const float* __restrict__ W2, const float* __restrict__ b2,
    const float* __restrict__ W3, const float* __restrict__ b3) {
    extern __shared__ float sm[];
    float* sW1 = sm;               // 32*64   = 2048
    float* sW2 = sW1 + 2048;       // 64*128  = 8192
    float* sW3 = sW2 + 8192;       // 128*192 = 24576
    float* sB1 = sW3 + 24576;      // 64
    float* sB2 = sB1 + 64;         // 128
    float* sB3 = sB2 + 128;        // 192
    float* sAt = sB3 + 192;        // 32*64  (edge_attr^T: [k][e])
    float* sH1 = sAt + 2048;       // 64*64  ([j][e])
    float* sH2 = sH1 + 4096;       // 128*64 ([j][e])
    float* sCw = sH2 + 8192;       // 64
    int* sSrc = reinterpret_cast<int*>(sCw + 64);  // 64
    int* sDst = sSrc + 64;                          // 64

    int tid = threadIdx.x;
    for (int i = tid; i < 2048; i += 256) sW1[i] = W1[i];
    for (int i = tid; i < 8192; i += 256) sW2[i] = W2[i];
    for (int i = tid; i < 24576; i += 256) sW3[i] = W3[i];
    if (tid < 64) sB1[tid] = b1[tid];
    if (tid < 128) sB2[tid] = b2[tid];
    if (tid < 192) sB3[tid] = b3[tid];
    __syncthreads();

    const int tx = tid & 15, ty = tid >> 4;
    const int e0 = tx * 4;
    const int nTiles = EE / 64;

    for (int tile = blockIdx.x; tile < nTiles; tile += gridDim.x) {
        int base = tile * 64;
        if (tid < 64) {
            int e = base + tid;
            sSrc[tid] = edge_index[e];
            sDst[tid] = edge_index[EE + e];
            float w = edge_weight[e];
            float cw = 0.5f * (__cosf(w * PI_OVER_CUT) + 1.0f);
            sCw[tid] = (w < CUTOFF_F) ? cw : 0.0f;
        }
        for (int i = tid; i < 512; i += 256) {
            int e = i >> 3, kq = i & 7;
            float4 v = __ldg(reinterpret_cast<const float4*>(edge_attr + ((size_t)(base + e)) * 32 + kq * 4));
            sAt[(kq * 4 + 0) * 64 + e] = v.x;
            sAt[(kq * 4 + 1) * 64 + e] = v.y;
            sAt[(kq * 4 + 2) * 64 + e] = v.z;
            sAt[(kq * 4 + 3) * 64 + e] = v.w;
        }
        __syncthreads();

        // ---- layer 1: [64e,32] @ [32,64] -> sH1[j][e]   (FFMA2, j-paired)
        {
            int j0 = ty * 4;
            unsigned long long acc[4][2];
            {
                ulonglong2 b = *(const ulonglong2*)&sB1[j0];
#pragma unroll
                for (int ee = 0; ee < 4; ee++) { acc[ee][0] = b.x; acc[ee][1] = b.y; }
            }
#pragma unroll 4
            for (int k = 0; k < 32; k++) {
                float4 av = *(const float4*)&sAt[k * 64 + e0];
                unsigned long long a2[4] = {pack2(av.x), pack2(av.y), pack2(av.z), pack2(av.w)};
                ulonglong2 w = *(const ulonglong2*)&sW1[k * 64 + j0];
#pragma unroll
                for (int ee = 0; ee < 4; ee++) { ffma2(acc[ee][0], a2[ee], w.x); ffma2(acc[ee][1], a2[ee], w.y); }
            }
#pragma unroll
            for (int q = 0; q < 2; q++) {
                float2 u[4];
#pragma unroll
                for (int ee = 0; ee < 4; ee++) u[ee] = unp2(acc[ee][q]);
                float4 o0 = make_float4(silu_f(u[0].x), silu_f(u[1].x), silu_f(u[2].x), silu_f(u[3].x));
                float4 o1 = make_float4(silu_f(u[0].y), silu_f(u[1].y), silu_f(u[2].y), silu_f(u[3].y));
                *(float4*)&sH1[(j0 + 2 * q) * 64 + e0] = o0;
                *(float4*)&sH1[(j0 + 2 * q + 1) * 64 + e0] = o1;
            }
        }
        __syncthreads();

        // ---- layer 2: [64e,64] @ [64,128] -> sH2[j][e]
        {
            int j0 = ty * 8;
            unsigned long long acc[4][4];
            {
                ulonglong2 ba = *(const ulonglong2*)&sB2[j0];
                ulonglong2 bb = *(const ulonglong2*)&sB2[j0 + 4];
#pragma unroll
                for (int ee = 0; ee < 4; ee++) { acc[ee][0] = ba.x; acc[ee][1] = ba.y; acc[ee][2] = bb.x; acc[ee][3] = bb.y; }
            }
#pragma unroll 2
            for (int k = 0; k < 64; k++) {
                float4 av = *(const float4*)&sH1[k * 64 + e0];
                unsigned long long a2[4] = {pack2(av.x), pack2(av.y), pack2(av.z), pack2(av.w)};
                ulonglong2 wa = *(const ulonglong2*)&sW2[k * 128 + j0];
                ulonglong2 wb = *(const ulonglong2*)&sW2[k * 128 + j0 + 4];
#pragma unroll
                for (int ee = 0; ee < 4; ee++) {
                    ffma2(acc[ee][0], a2[ee], wa.x); ffma2(acc[ee][1], a2[ee], wa.y);
                    ffma2(acc[ee][2], a2[ee], wb.x); ffma2(acc[ee][3], a2[ee], wb.y);
                }
            }
#pragma unroll
            for (int q = 0; q < 4; q++) {
                float2 u[4];
#pragma unroll
                for (int ee = 0; ee < 4; ee++) u[ee] = unp2(acc[ee][q]);
                float4 o0 = make_float4(silu_f(u[0].x), silu_f(u[1].x), silu_f(u[2].x), silu_f(u[3].x));
                float4 o1 = make_float4(silu_f(u[0].y), silu_f(u[1].y), silu_f(u[2].y), silu_f(u[3].y));
                *(float4*)&sH2[(j0 + 2 * q) * 64 + e0] = o0;
                *(float4*)&sH2[(j0 + 2 * q + 1) * 64 + e0] = o1;
            }
        }
        __syncthreads();

        // ---- layer 3: [64e,128] @ [128,192] + fused scatter epilogue
        {
            int j0 = ty * 12;
            unsigned long long acc[4][6];
            {
                ulonglong2 ba = *(const ulonglong2*)&sB3[j0];
                ulonglong2 bb = *(const ulonglong2*)&sB3[j0 + 4];
                ulonglong2 bc = *(const ulonglong2*)&sB3[j0 + 8];
#pragma unroll
                for (int ee = 0; ee < 4; ee++) {
                    acc[ee][0] = ba.x; acc[ee][1] = ba.y;
                    acc[ee][2] = bb.x; acc[ee][3] = bb.y;
                    acc[ee][4] = bc.x; acc[ee][5] = bc.y;
                }
            }
#pragma unroll 2
            for (int k = 0; k < 128; k++) {
                float4 av = *(const float4*)&sH2[k * 64 + e0];
                unsigned long long a2[4] = {pack2(av.x), pack2(av.y), pack2(av.z), pack2(av.w)};
                ulonglong2 wa = *(const ulonglong2*)&sW3[k * 192 + j0];
                ulonglong2 wb = *(const ulonglong2*)&sW3[k * 192 + j0 + 4];
                ulonglong2 wc = *(const ulonglong2*)&sW3[k * 192 + j0 + 8];
#pragma unroll
                for (int ee = 0; ee < 4; ee++) {
                    ffma2(acc[ee][0], a2[ee], wa.x); ffma2(acc[ee][1], a2[ee], wa.y);
                    ffma2(acc[ee][2], a2[ee], wb.x); ffma2(acc[ee][3], a2[ee], wb.y);
                    ffma2(acc[ee][4], a2[ee], wc.x); ffma2(acc[ee][5], a2[ee], wc.y);
                }
            }
#pragma unroll
            for (int ee = 0; ee < 4; ee++) {
                float accf[12];
#pragma unroll
                for (int q = 0; q < 6; q++) {
                    float2 u = unp2(acc[ee][q]);
                    accf[2 * q] = u.x; accf[2 * q + 1] = u.y;
                }
                int e = e0 + ee;
                float cw = sCw[e];
                int s = sSrc[e], d = sDst[e];
#pragma unroll
                for (int cc = 0; cc < 4; cc++) {
                    int c = ty * 4 + cc;
                    float fI = silu_f(accf[cc * 3 + 0]) * cw;
                    float fA = silu_f(accf[cc * 3 + 1]) * cw;
                    float fS = silu_f(accf[cc * 3 + 2]) * cw;
                    const float4* p = reinterpret_cast<const float4*>(g_comp + ((size_t)d * 64 + c) * 12);
                    float4 v0 = __ldg(p), v1 = __ldg(p + 1), v2 = __ldg(p + 2);
                    float* q = g_msg + ((size_t)s * 64 + c) * 12;
                    red4(q, fI * v0.x, fA * v0.y, fA * v0.z, fA * v0.w);
                    red4(q + 4, fS * v1.x, fS * v1.y, fS * v1.z, fS * v1.w);
                    red2(q + 8, fS * v2.x, fS * v2.y);
                }
            }
        }
        __syncthreads();
    }
}

// ---------------------------------------------------------------- node post
__global__ void __launch_bounds__(256) k_node_post(const float* __restrict__ Wt,
                                                   float* __restrict__ out) {
    extern __shared__ float sm[];
    float* sW = sm;              // 3*4096 (Wt3, Wt4, Wt5)
    float* sc = sW + 3 * 4096;   // 10 * NPB*64 (planar)

    const int PL = NPB * 64;
    int tid = threadIdx.x;
    for (int i = tid; i < 3 * 4096; i += 256) sW[i] = Wt[3 * 4096 + i];

    int n0 = blockIdx.x * NPB;

    for (int idx = tid; idx < NPB * CC; idx += 256) {
        int ni = idx >> 6, c = idx & 63;
        int n = n0 + ni;
        if (n < NN) {
            const float4* mp = reinterpret_cast<const float4*>(g_msg + ((size_t)n * 64 + c) * 12);
            float4 m0 = mp[0], m1 = mp[1], m2 = mp[2];
            const float4* yp = reinterpret_cast<const float4*>(g_comp + ((size_t)n * 64 + c) * 12);
            float4 y0 = yp[0], y1 = yp[1], y2 = yp[2];
            float Mg[3][3], Y[3][3];
            build_mat(Mg, m0.x, m0.y, m0.z, m0.w, m1.x, m1.y, m1.z, m1.w, m2.x, m2.y);
            build_mat(Y, y0.x, y0.y, y0.z, y0.w, y1.x, y1.y, y1.z, y1.w, y2.x, y2.y);
            float P[3][3];
#pragma unroll
            for (int i = 0; i < 3; i++)
#pragma unroll
                for (int j = 0; j < 3; j++) {
                    float v = 0.f;
#pragma unroll
                    for (int k = 0; k < 3; k++) v += Mg[i][k] * Y[k][j] + Y[i][k] * Mg[k][j];
                    P[i][j] = v;
                }
            float nrm = 0.f;
#pragma unroll
            for (int i = 0; i < 3; i++)
#pragma unroll
                for (int j = 0; j < 3; j++) nrm += P[i][j] * P[i][j];
            float inv = 1.0f / (nrm + 1.0f);
            float ic = (P[0][0] + P[1][1] + P[2][2]) * (1.0f / 3.0f);
            int o = ni * 64 + c;
            sc[0 * PL + o] = ic * inv;
            sc[1 * PL + o] = 0.5f * (P[0][1] - P[1][0]) * inv;
            sc[2 * PL + o] = 0.5f * (P[0][2] - P[2][0]) * inv;
            sc[3 * PL + o] = 0.5f * (P[1][2] - P[2][1]) * inv;
            sc[4 * PL + o] = (P[0][0] - ic) * inv;
            sc[5 * PL + o] = 0.5f * (P[0][1] + P[1][0]) * inv;
            sc[6 * PL + o] = 0.5f * (P[0][2] + P[2][0]) * inv;
            sc[7 * PL + o] = (P[1][1] - ic) * inv;
            sc[8 * PL + o] = 0.5f * (P[1][2] + P[2][1]) * inv;
            sc[9 * PL + o] = (P[2][2] - ic) * inv;
        }
    }
    __syncthreads();

    {
        int ni = tid >> 5, g = tid & 31;
        int j0 = g * 2;
        int n = n0 + ni;
        if (n >= NN) return;
        float aI[2] = {0, 0};
        float aA[3][2] = {};
        float aS[6][2] = {};
        const float* scb = sc + ni * 64;
#pragma unroll 4
        for (int k = 0; k < 64; k++) {
            float c10[10];
#pragma unroll
            for (int q = 0; q < 10; q++) c10[q] = scb[q * PL + k];
            float2 w0 = *(const float2*)&sW[k * 64 + j0];
            float2 w1 = *(const float2*)&sW[4096 + k * 64 + j0];
            float2 w2 = *(const float2*)&sW[8192 + k * 64 + j0];
            aI[0] += c10[0] * w0.x; aI[1] += c10[0] * w0.y;
#pragma unroll
            for (int i = 0; i < 3; i++) { aA[i][0] += c10[1 + i] * w1.x; aA[i][1] += c10[1 + i] * w1.y; }
#pragma unroll
            for (int i = 0; i < 6; i++) { aS[i][0] += c10[4 + i] * w2.x; aS[i][1] += c10[4 + i] * w2.y; }
        }
#pragma unroll
        for (int j = 0; j < 2; j++) {
            int l = j0 + j;
            float D[3][3];
            build_mat(D, aI[j], aA[0][j], aA[1][j], aA[2][j],
                      aS[0][j], aS[1][j], aS[2][j], aS[3][j], aS[4][j], aS[5][j]);
            const float* xp = g_Xn + ((size_t)n * 64 + l) * 9;
            float* op = out + ((size_t)n * 64 + l) * 9;
#pragma unroll
            for (int i = 0; i < 3; i++)
#pragma unroll
                for (int j2 = 0; j2 < 3; j2++) {
                    float dd = 0.f;
#pragma unroll
                    for (int k = 0; k < 3; k++) dd += D[i][k] * D[k][j2];
                    op[i * 3 + j2] = __ldg(xp + i * 3 + j2) + D[i][j2] + dd;
                }
        }
    }
}

// ---------------------------------------------------------------- launch
extern "C" void kernel_launch(void* const* d_in, const int* in_sizes, int n_in,
                              void* d_out, int out_size) {
    const float* X  = (const float*)d_in[0];
    const int*   ei = (const int*)d_in[1];
    const float* ew = (const float*)d_in[2];
    const float* ea = (const float*)d_in[3];
    const float* W1 = (const float*)d_in[4];
    const float* b1 = (const float*)d_in[5];
    const float* W2 = (const float*)d_in[6];
    const float* b2 = (const float*)d_in[7];
    const float* W3 = (const float*)d_in[8];
    const float* b3 = (const float*)d_in[9];
    const float* Wt = (const float*)d_in[10];
    float* out = (float*)d_out;

    const int smNode = (3 * 4096 + NPB * 64 * 10) * 4;                 // ~68 KB
    const int smEdge = (2048 + 8192 + 24576 + 64 + 128 + 192 + 2048 +
                        4096 + 8192 + 64 + 128) * 4;                    // ~194 KB

    cudaFuncSetAttribute(k_node_pre, cudaFuncAttributeMaxDynamicSharedMemorySize, smNode);
    cudaFuncSetAttribute(k_node_post, cudaFuncAttributeMaxDynamicSharedMemorySize, smNode);
    cudaFuncSetAttribute(k_edge, cudaFuncAttributeMaxDynamicSharedMemorySize, smEdge);

    k_zero<<<256, 256>>>();
    k_node_pre<<<(NN + NPB - 1) / NPB, 256, smNode>>>(X, Wt);
    k_edge<<<148, 256, smEdge>>>(ea, ei, ew, W1, b1, W2, b2, W3, b3);
    k_node_post<<<(NN + NPB - 1) / NPB, 256, smNode>>>(Wt, out);
}

// round 3
// speedup vs baseline: 1.1586x; 1.0779x over previous
#include <cuda_runtime.h>
#include <math.h>
#include <stdint.h>

#define NN 10000
#define EE 160000
#define CC 64
#define RR 32
#define NPB 8
constexpr float CUTOFF_F = 5.0f;
constexpr float PI_OVER_CUT = 0.62831853071795864769f; // pi/5

typedef unsigned long long ull;

// Scratch (device globals; no runtime allocation allowed)
__device__ float g_Xn[(size_t)NN * CC * 9];        // normalized node tensors
__device__ float g_comp[(size_t)NN * CC * 12];     // mixed I/A/S compact
__device__ float g_msg[(size_t)NN * CC * 12];      // accumulated messages

__device__ __forceinline__ float silu_f(float x) { return x / (1.0f + __expf(-x)); }

__device__ __forceinline__ void red4(float* p, float a, float b, float c, float d) {
    asm volatile("red.global.add.v4.f32 [%0], {%1,%2,%3,%4};"
                 :: "l"(p), "f"(a), "f"(b), "f"(c), "f"(d) : "memory");
}
__device__ __forceinline__ void red2(float* p, float a, float b) {
    asm volatile("red.global.add.v2.f32 [%0], {%1,%2};"
                 :: "l"(p), "f"(a), "f"(b) : "memory");
}

// ---- packed fp32x2 helpers (Blackwell FFMA2) ----
__device__ __forceinline__ ull pack2(float x) {
    ull r;
    asm("mov.b64 %0, {%1, %1};" : "=l"(r) : "f"(x));
    return r;
}
__device__ __forceinline__ void ffma2(ull& d, ull a, ull b) {
    asm("fma.rn.f32x2 %0, %1, %2, %0;" : "+l"(d) : "l"(a), "l"(b));
}
__device__ __forceinline__ float2 unp2(ull v) {
    float2 f;
    asm("mov.b64 {%0, %1}, %2;" : "=f"(f.x), "=f"(f.y) : "l"(v));
    return f;
}
__device__ __forceinline__ ull lds64(const float* p) {
    ull r;
    asm("ld.shared.b64 %0, [%1];" : "=l"(r) : "l"(__cvta_generic_to_shared(p)));
    return r;
}

// Build full 3x3 from compact comps
__device__ __forceinline__ void build_mat(float M[3][3], float ic, float a0, float a1, float a2,
                                          float s00, float s01, float s02, float s11, float s12, float s22) {
    M[0][0] = ic + s00;  M[0][1] = a0 + s01;  M[0][2] = a1 + s02;
    M[1][0] = -a0 + s01; M[1][1] = ic + s11;  M[1][2] = a2 + s12;
    M[2][0] = -a1 + s02; M[2][1] = -a2 + s12; M[2][2] = ic + s22;
}

// ---------------------------------------------------------------- zero msg
__global__ void k_zero() {
    size_t i = (size_t)blockIdx.x * blockDim.x + threadIdx.x;
    const size_t total = (size_t)NN * CC * 12 / 4;
    float4 z = make_float4(0.f, 0.f, 0.f, 0.f);
    for (; i < total; i += (size_t)gridDim.x * blockDim.x)
        reinterpret_cast<float4*>(g_msg)[i] = z;
}

// ---------------------------------------------------------------- node pre
__global__ void __launch_bounds__(256) k_node_pre(const float* __restrict__ X,
                                                  const float* __restrict__ Wt) {
    extern __shared__ float sm[];
    float* sW = sm;              // 3*4096 floats (Wt0, Wt1, Wt2)
    float* sc = sW + 3 * 4096;   // 10 * NPB*64 (planar)

    const int PL = NPB * 64;
    int tid = threadIdx.x;
    for (int i = tid; i < 3 * 4096; i += 256) sW[i] = Wt[i];

    int n0 = blockIdx.x * NPB;

    for (int idx = tid; idx < NPB * CC; idx += 256) {
        int ni = idx >> 6, c = idx & 63;
        int n = n0 + ni;
        if (n < NN) {
            const float* xp = X + ((size_t)n * CC + c) * 9;
            float x[9];
#pragma unroll
            for (int i = 0; i < 9; i++) x[i] = __ldg(xp + i);
            float nrm = 0.f;
#pragma unroll
            for (int i = 0; i < 9; i++) nrm += x[i] * x[i];
            float inv = 1.0f / (nrm + 1.0f);
            float xn[9];
#pragma unroll
            for (int i = 0; i < 9; i++) xn[i] = x[i] * inv;
            float* op = g_Xn + ((size_t)n * CC + c) * 9;
#pragma unroll
            for (int i = 0; i < 9; i++) op[i] = xn[i];
            float ic = (xn[0] + xn[4] + xn[8]) * (1.0f / 3.0f);
            int o = ni * 64 + c;
            sc[0 * PL + o] = ic;
            sc[1 * PL + o] = 0.5f * (xn[1] - xn[3]);
            sc[2 * PL + o] = 0.5f * (xn[2] - xn[6]);
            sc[3 * PL + o] = 0.5f * (xn[5] - xn[7]);
            sc[4 * PL + o] = xn[0] - ic;
            sc[5 * PL + o] = 0.5f * (xn[1] + xn[3]);
            sc[6 * PL + o] = 0.5f * (xn[2] + xn[6]);
            sc[7 * PL + o] = xn[4] - ic;
            sc[8 * PL + o] = 0.5f * (xn[5] + xn[7]);
            sc[9 * PL + o] = xn[8] - ic;
        }
    }
    __syncthreads();

    {
        int ni = tid >> 5, g = tid & 31;
        int j0 = g * 2;
        int n = n0 + ni;
        if (n >= NN) return;
        float aI[2] = {0, 0};
        float aA[3][2] = {};
        float aS[6][2] = {};
        const float* scb = sc + ni * 64;
#pragma unroll 4
        for (int k = 0; k < 64; k++) {
            float c10[10];
#pragma unroll
            for (int q = 0; q < 10; q++) c10[q] = scb[q * PL + k];
            float2 w0 = *(const float2*)&sW[k * 64 + j0];
            float2 w1 = *(const float2*)&sW[4096 + k * 64 + j0];
            float2 w2 = *(const float2*)&sW[8192 + k * 64 + j0];
            aI[0] += c10[0] * w0.x; aI[1] += c10[0] * w0.y;
#pragma unroll
            for (int i = 0; i < 3; i++) { aA[i][0] += c10[1 + i] * w1.x; aA[i][1] += c10[1 + i] * w1.y; }
#pragma unroll
            for (int i = 0; i < 6; i++) { aS[i][0] += c10[4 + i] * w2.x; aS[i][1] += c10[4 + i] * w2.y; }
        }
#pragma unroll
        for (int j = 0; j < 2; j++) {
            int l = j0 + j;
            float4* q = reinterpret_cast<float4*>(g_comp + ((size_t)n * 64 + l) * 12);
            q[0] = make_float4(aI[j], aA[0][j], aA[1][j], aA[2][j]);
            q[1] = make_float4(aS[0][j], aS[1][j], aS[2][j], aS[3][j]);
            q[2] = make_float4(aS[4][j], aS[5][j], 0.f, 0.f);
        }
    }
}

// ---------------------------------------------------------------- edge kernel
// Persistent, 512 threads (16 warps -> 4/SMSP for latency hiding).
// 64-edge tiles; fused 3-layer MLP (FFMA2) + gather/scatter epilogue.
__global__ void __launch_bounds__(512, 1) k_edge(
    const float* __restrict__ edge_attr, const int* __restrict__ edge_index,
    const float* __restrict__ edge_weight,
    const float* __restrict__ W1, const float* __restrict__ b1,
    const float* __restrict__ W2, const float* __restrict__ b2,
    const float* __restrict__ W3, const float* __restrict__ b3) {
    extern __shared__ float sm[];
    float* sW1 = sm;               // 32*64   = 2048
    float* sW2 = sW1 + 2048;       // 64*128  = 8192
    float* sW3 = sW2 + 8192;       // 128*192 = 24576
    float* sB1 = sW3 + 24576;      // 64
    float* sB2 = sB1 + 64;         // 128
    float* sB3 = sB2 + 128;        // 192
    float* sAt = sB3 + 192;        // 32*64  (edge_attr^T: [k][e])
    float* sH1 = sAt + 2048;       // 64*64  ([j][e])
    float* sH2 = sH1 + 4096;       // 128*64 ([j][e])
    float* sCw = sH2 + 8192;       // 64
    int* sSrc = reinterpret_cast<int*>(sCw + 64);  // 64
    int* sDst = sSrc + 64;                          // 64

    int tid = threadIdx.x;
    for (int i = tid; i < 2048; i += 512) sW1[i] = W1[i];
    for (int i = tid; i < 8192; i += 512) sW2[i] = W2[i];
    for (int i = tid; i < 24576; i += 512) sW3[i] = W3[i];
    if (tid < 64) sB1[tid] = b1[tid];
    else if (tid < 192) sB2[tid - 64] = b2[tid - 64];
    else if (tid < 384) sB3[tid - 192] = b3[tid - 192];
    __syncthreads();

    const int tx = tid & 15, ty = tid >> 4;   // ty in [0,32)
    const int e0 = tx * 4;
    const int nTiles = EE / 64;

    for (int tile = blockIdx.x; tile < nTiles; tile += gridDim.x) {
        int base = tile * 64;
        if (tid < 64) {
            int e = base + tid;
            sSrc[tid] = edge_index[e];
            sDst[tid] = edge_index[EE + e];
            float w = edge_weight[e];
            float cw = 0.5f * (__cosf(w * PI_OVER_CUT) + 1.0f);
            sCw[tid] = (w < CUTOFF_F) ? cw : 0.0f;
        }
        for (int i = tid; i < 512; i += 512) {
            int e = i >> 3, kq = i & 7;
            float4 v = __ldg(reinterpret_cast<const float4*>(edge_attr + ((size_t)(base + e)) * 32 + kq * 4));
            sAt[(kq * 4 + 0) * 64 + e] = v.x;
            sAt[(kq * 4 + 1) * 64 + e] = v.y;
            sAt[(kq * 4 + 2) * 64 + e] = v.z;
            sAt[(kq * 4 + 3) * 64 + e] = v.w;
        }
        __syncthreads();

        // ---- layer 1: [64e,32] @ [32,64] -> sH1[j][e]   j-slice = 2 per thread
        {
            int j0 = ty * 2;
            ull acc[4];
            {
                ull b = lds64(&sB1[j0]);
#pragma unroll
                for (int ee = 0; ee < 4; ee++) acc[ee] = b;
            }
#pragma unroll 4
            for (int k = 0; k < 32; k++) {
                float4 av = *(const float4*)&sAt[k * 64 + e0];
                ull w = lds64(&sW1[k * 64 + j0]);
                ffma2(acc[0], pack2(av.x), w);
                ffma2(acc[1], pack2(av.y), w);
                ffma2(acc[2], pack2(av.z), w);
                ffma2(acc[3], pack2(av.w), w);
            }
            float2 u[4];
#pragma unroll
            for (int ee = 0; ee < 4; ee++) u[ee] = unp2(acc[ee]);
            *(float4*)&sH1[j0 * 64 + e0] =
                make_float4(silu_f(u[0].x), silu_f(u[1].x), silu_f(u[2].x), silu_f(u[3].x));
            *(float4*)&sH1[(j0 + 1) * 64 + e0] =
                make_float4(silu_f(u[0].y), silu_f(u[1].y), silu_f(u[2].y), silu_f(u[3].y));
        }
        __syncthreads();

        // ---- layer 2: [64e,64] @ [64,128] -> sH2[j][e]   j-slice = 4
        {
            int j0 = ty * 4;
            ull acc[4][2];
            {
                ulonglong2 b = *(const ulonglong2*)&sB2[j0];
#pragma unroll
                for (int ee = 0; ee < 4; ee++) { acc[ee][0] = b.x; acc[ee][1] = b.y; }
            }
#pragma unroll 4
            for (int k = 0; k < 64; k++) {
                float4 av = *(const float4*)&sH1[k * 64 + e0];
                ulonglong2 w = *(const ulonglong2*)&sW2[k * 128 + j0];
                ull a2[4] = {pack2(av.x), pack2(av.y), pack2(av.z), pack2(av.w)};
#pragma unroll
                for (int ee = 0; ee < 4; ee++) { ffma2(acc[ee][0], a2[ee], w.x); ffma2(acc[ee][1], a2[ee], w.y); }
            }
#pragma unroll
            for (int q = 0; q < 2; q++) {
                float2 u[4];
#pragma unroll
                for (int ee = 0; ee < 4; ee++) u[ee] = unp2(acc[ee][q]);
                *(float4*)&sH2[(j0 + 2 * q) * 64 + e0] =
                    make_float4(silu_f(u[0].x), silu_f(u[1].x), silu_f(u[2].x), silu_f(u[3].x));
                *(float4*)&sH2[(j0 + 2 * q + 1) * 64 + e0] =
                    make_float4(silu_f(u[0].y), silu_f(u[1].y), silu_f(u[2].y), silu_f(u[3].y));
            }
        }
        __syncthreads();

        // ---- layer 3: [64e,128] @ [128,192] + fused scatter   j-slice = 6 (2 channels)
        {
            int j0 = ty * 6;
            ull acc[4][3];
            {
                ull b0 = lds64(&sB3[j0]), b1v = lds64(&sB3[j0 + 2]), b2v = lds64(&sB3[j0 + 4]);
#pragma unroll
                for (int ee = 0; ee < 4; ee++) { acc[ee][0] = b0; acc[ee][1] = b1v; acc[ee][2] = b2v; }
            }
#pragma unroll 4
            for (int k = 0; k < 128; k++) {
                float4 av = *(const float4*)&sH2[k * 64 + e0];
                ull w0 = lds64(&sW3[k * 192 + j0]);
                ull w1 = lds64(&sW3[k * 192 + j0 + 2]);
                ull w2 = lds64(&sW3[k * 192 + j0 + 4]);
                ull a2[4] = {pack2(av.x), pack2(av.y), pack2(av.z), pack2(av.w)};
#pragma unroll
                for (int ee = 0; ee < 4; ee++) {
                    ffma2(acc[ee][0], a2[ee], w0);
                    ffma2(acc[ee][1], a2[ee], w1);
                    ffma2(acc[ee][2], a2[ee], w2);
                }
            }
#pragma unroll
            for (int ee = 0; ee < 4; ee++) {
                float accf[6];
#pragma unroll
                for (int q = 0; q < 3; q++) {
                    float2 u = unp2(acc[ee][q]);
                    accf[2 * q] = u.x; accf[2 * q + 1] = u.y;
                }
                int e = e0 + ee;
                float cw = sCw[e];
                int s = sSrc[e], d = sDst[e];
#pragma unroll
                for (int cc = 0; cc < 2; cc++) {
                    int c = ty * 2 + cc;
                    float fI = silu_f(accf[cc * 3 + 0]) * cw;
                    float fA = silu_f(accf[cc * 3 + 1]) * cw;
                    float fS = silu_f(accf[cc * 3 + 2]) * cw;
                    const float4* p = reinterpret_cast<const float4*>(g_comp + ((size_t)d * 64 + c) * 12);
                    float4 v0 = __ldg(p), v1 = __ldg(p + 1), v2 = __ldg(p + 2);
                    float* q = g_msg + ((size_t)s * 64 + c) * 12;
                    red4(q, fI * v0.x, fA * v0.y, fA * v0.z, fA * v0.w);
                    red4(q + 4, fS * v1.x, fS * v1.y, fS * v1.z, fS * v1.w);
                    red2(q + 8, fS * v2.x, fS * v2.y);
                }
            }
        }
        __syncthreads();
    }
}

// ---------------------------------------------------------------- node post
__global__ void __launch_bounds__(256) k_node_post(const float* __restrict__ Wt,
                                                   float* __restrict__ out) {
    extern __shared__ float sm[];
    float* sW = sm;              // 3*4096 (Wt3, Wt4, Wt5)
    float* sc = sW + 3 * 4096;   // 10 * NPB*64 (planar)

    const int PL = NPB * 64;
    int tid = threadIdx.x;
    for (int i = tid; i < 3 * 4096; i += 256) sW[i] = Wt[3 * 4096 + i];

    int n0 = blockIdx.x * NPB;

    for (int idx = tid; idx < NPB * CC; idx += 256) {
        int ni = idx >> 6, c = idx & 63;
        int n = n0 + ni;
        if (n < NN) {
            const float4* mp = reinterpret_cast<const float4*>(g_msg + ((size_t)n * 64 + c) * 12);
            float4 m0 = mp[0], m1 = mp[1], m2 = mp[2];
            const float4* yp = reinterpret_cast<const float4*>(g_comp + ((size_t)n * 64 + c) * 12);
            float4 y0 = yp[0], y1 = yp[1], y2 = yp[2];
            float Mg[3][3], Y[3][3];
            build_mat(Mg, m0.x, m0.y, m0.z, m0.w, m1.x, m1.y, m1.z, m1.w, m2.x, m2.y);
            build_mat(Y, y0.x, y0.y, y0.z, y0.w, y1.x, y1.y, y1.z, y1.w, y2.x, y2.y);
            float P[3][3];
#pragma unroll
            for (int i = 0; i < 3; i++)
#pragma unroll
                for (int j = 0; j < 3; j++) {
                    float v = 0.f;
#pragma unroll
                    for (int k = 0; k < 3; k++) v += Mg[i][k] * Y[k][j] + Y[i][k] * Mg[k][j];
                    P[i][j] = v;
                }
            float nrm = 0.f;
#pragma unroll
            for (int i = 0; i < 3; i++)
#pragma unroll
                for (int j = 0; j < 3; j++) nrm += P[i][j] * P[i][j];
            float inv = 1.0f / (nrm + 1.0f);
            float ic = (P[0][0] + P[1][1] + P[2][2]) * (1.0f / 3.0f);
            int o = ni * 64 + c;
            sc[0 * PL + o] = ic * inv;
            sc[1 * PL + o] = 0.5f * (P[0][1] - P[1][0]) * inv;
            sc[2 * PL + o] = 0.5f * (P[0][2] - P[2][0]) * inv;
            sc[3 * PL + o] = 0.5f * (P[1][2] - P[2][1]) * inv;
            sc[4 * PL + o] = (P[0][0] - ic) * inv;
            sc[5 * PL + o] = 0.5f * (P[0][1] + P[1][0]) * inv;
            sc[6 * PL + o] = 0.5f * (P[0][2] + P[2][0]) * inv;
            sc[7 * PL + o] = (P[1][1] - ic) * inv;
            sc[8 * PL + o] = 0.5f * (P[1][2] + P[2][1]) * inv;
            sc[9 * PL + o] = (P[2][2] - ic) * inv;
        }
    }
    __syncthreads();

    {
        int ni = tid >> 5, g = tid & 31;
        int j0 = g * 2;
        int n = n0 + ni;
        if (n >= NN) return;
        float aI[2] = {0, 0};
        float aA[3][2] = {};
        float aS[6][2] = {};
        const float* scb = sc + ni * 64;
#pragma unroll 4
        for (int k = 0; k < 64; k++) {
            float c10[10];
#pragma unroll
            for (int q = 0; q < 10; q++) c10[q] = scb[q * PL + k];
            float2 w0 = *(const float2*)&sW[k * 64 + j0];
            float2 w1 = *(const float2*)&sW[4096 + k * 64 + j0];
            float2 w2 = *(const float2*)&sW[8192 + k * 64 + j0];
            aI[0] += c10[0] * w0.x; aI[1] += c10[0] * w0.y;
#pragma unroll
            for (int i = 0; i < 3; i++) { aA[i][0] += c10[1 + i] * w1.x; aA[i][1] += c10[1 + i] * w1.y; }
#pragma unroll
            for (int i = 0; i < 6; i++) { aS[i][0] += c10[4 + i] * w2.x; aS[i][1] += c10[4 + i] * w2.y; }
        }
#pragma unroll
        for (int j = 0; j < 2; j++) {
            int l = j0 + j;
            float D[3][3];
            build_mat(D, aI[j], aA[0][j], aA[1][j], aA[2][j],
                      aS[0][j], aS[1][j], aS[2][j], aS[3][j], aS[4][j], aS[5][j]);
            const float* xp = g_Xn + ((size_t)n * 64 + l) * 9;
            float* op = out + ((size_t)n * 64 + l) * 9;
#pragma unroll
            for (int i = 0; i < 3; i++)
#pragma unroll
                for (int j2 = 0; j2 < 3; j2++) {
                    float dd = 0.f;
#pragma unroll
                    for (int k = 0; k < 3; k++) dd += D[i][k] * D[k][j2];
                    op[i * 3 + j2] = __ldg(xp + i * 3 + j2) + D[i][j2] + dd;
                }
        }
    }
}

// ---------------------------------------------------------------- launch
extern "C" void kernel_launch(void* const* d_in, const int* in_sizes, int n_in,
                              void* d_out, int out_size) {
    const float* X  = (const float*)d_in[0];
    const int*   ei = (const int*)d_in[1];
    const float* ew = (const float*)d_in[2];
    const float* ea = (const float*)d_in[3];
    const float* W1 = (const float*)d_in[4];
    const float* b1 = (const float*)d_in[5];
    const float* W2 = (const float*)d_in[6];
    const float* b2 = (const float*)d_in[7];
    const float* W3 = (const float*)d_in[8];
    const float* b3 = (const float*)d_in[9];
    const float* Wt = (const float*)d_in[10];
    float* out = (float*)d_out;

    const int smNode = (3 * 4096 + NPB * 64 * 10) * 4;                 // ~68 KB
    const int smEdge = (2048 + 8192 + 24576 + 64 + 128 + 192 + 2048 +
                        4096 + 8192 + 64 + 128) * 4;                    // ~194 KB

    cudaFuncSetAttribute(k_node_pre, cudaFuncAttributeMaxDynamicSharedMemorySize, smNode);
    cudaFuncSetAttribute(k_node_post, cudaFuncAttributeMaxDynamicSharedMemorySize, smNode);
    cudaFuncSetAttribute(k_edge, cudaFuncAttributeMaxDynamicSharedMemorySize, smEdge);

    k_zero<<<256, 256>>>();
    k_node_pre<<<(NN + NPB - 1) / NPB, 256, smNode>>>(X, Wt);
    k_edge<<<148, 512, smEdge>>>(ea, ei, ew, W1, b1, W2, b2, W3, b3);
    k_node_post<<<(NN + NPB - 1) / NPB, 256, smNode>>>(Wt, out);
}

// round 4
// speedup vs baseline: 1.2980x; 1.1203x over previous
#include <cuda_runtime.h>
#include <math.h>
#include <stdint.h>

#define NN 10000
#define EE 160000
#define CC 64
#define RR 32
#define NPB 8
constexpr float CUTOFF_F = 5.0f;
constexpr float PI_OVER_CUT = 0.62831853071795864769f; // pi/5

typedef unsigned long long ull;

// Scratch (device globals; no runtime allocation allowed)
__device__ float g_Xn[(size_t)NN * CC * 9];        // normalized node tensors
__device__ float g_comp[(size_t)NN * CC * 12];     // mixed I/A/S compact
__device__ float g_msg[(size_t)NN * CC * 12];      // accumulated messages
__device__ float g_f[(size_t)EE * 192];            // per-edge factors (silu*cw)
__device__ int   g_deg[NN];
__device__ int   g_off[NN];
__device__ int   g_pos[NN];
__device__ int   g_eid[EE];
__device__ int   g_cdst[EE];

__device__ __forceinline__ float silu_f(float x) { return x / (1.0f + __expf(-x)); }

// ---- packed fp32x2 helpers (Blackwell FFMA2) ----
__device__ __forceinline__ ull pack2(float x) {
    ull r;
    asm("mov.b64 %0, {%1, %1};" : "=l"(r) : "f"(x));
    return r;
}
__device__ __forceinline__ void ffma2(ull& d, ull a, ull b) {
    asm("fma.rn.f32x2 %0, %1, %2, %0;" : "+l"(d) : "l"(a), "l"(b));
}
__device__ __forceinline__ float2 unp2(ull v) {
    float2 f;
    asm("mov.b64 {%0, %1}, %2;" : "=f"(f.x), "=f"(f.y) : "l"(v));
    return f;
}
__device__ __forceinline__ ull lds64(const float* p) {
    ull r;
    asm("ld.shared.b64 %0, [%1];" : "=l"(r) : "l"(__cvta_generic_to_shared(p)));
    return r;
}

// Build full 3x3 from compact comps
__device__ __forceinline__ void build_mat(float M[3][3], float ic, float a0, float a1, float a2,
                                          float s00, float s01, float s02, float s11, float s12, float s22) {
    M[0][0] = ic + s00;  M[0][1] = a0 + s01;  M[0][2] = a1 + s02;
    M[1][0] = -a0 + s01; M[1][1] = ic + s11;  M[1][2] = a2 + s12;
    M[2][0] = -a1 + s02; M[2][1] = -a2 + s12; M[2][2] = ic + s22;
}

// ---------------------------------------------------------------- CSR build
__global__ void k_zero_deg() {
    int i = blockIdx.x * blockDim.x + threadIdx.x;
    if (i < NN) g_deg[i] = 0;
}
__global__ void k_hist(const int* __restrict__ edge_index) {
    int e = blockIdx.x * blockDim.x + threadIdx.x;
    if (e < EE) atomicAdd(&g_deg[edge_index[e]], 1);
}
__global__ void __launch_bounds__(1024) k_scan() {
    __shared__ int s[1024];
    __shared__ int carry;
    int tid = threadIdx.x;
    if (tid == 0) carry = 0;
    __syncthreads();
    for (int base = 0; base < NN; base += 1024) {
        int i = base + tid;
        int v = (i < NN) ? g_deg[i] : 0;
        s[tid] = v;
        __syncthreads();
#pragma unroll
        for (int o = 1; o < 1024; o <<= 1) {
            int t = (tid >= o) ? s[tid - o] : 0;
            __syncthreads();
            s[tid] += t;
            __syncthreads();
        }
        int incl = s[tid];
        int excl = incl - v + carry;
        if (i < NN) { g_off[i] = excl; g_pos[i] = excl; }
        __syncthreads();
        if (tid == 1023) carry += incl;
        __syncthreads();
    }
}
__global__ void k_fill(const int* __restrict__ edge_index) {
    int e = blockIdx.x * blockDim.x + threadIdx.x;
    if (e < EE) {
        int srec = edge_index[e];
        int pos = atomicAdd(&g_pos[srec], 1);
        g_eid[pos] = e;
        g_cdst[pos] = edge_index[EE + e];
    }
}

// ---------------------------------------------------------------- node pre
__global__ void __launch_bounds__(256) k_node_pre(const float* __restrict__ X,
                                                  const float* __restrict__ Wt) {
    extern __shared__ float sm[];
    float* sW = sm;              // 3*4096 floats (Wt0, Wt1, Wt2)
    float* sc = sW + 3 * 4096;   // 10 * NPB*64 (planar)

    const int PL = NPB * 64;
    int tid = threadIdx.x;
    for (int i = tid; i < 3 * 4096; i += 256) sW[i] = Wt[i];

    int n0 = blockIdx.x * NPB;

    for (int idx = tid; idx < NPB * CC; idx += 256) {
        int ni = idx >> 6, c = idx & 63;
        int n = n0 + ni;
        if (n < NN) {
            const float* xp = X + ((size_t)n * CC + c) * 9;
            float x[9];
#pragma unroll
            for (int i = 0; i < 9; i++) x[i] = __ldg(xp + i);
            float nrm = 0.f;
#pragma unroll
            for (int i = 0; i < 9; i++) nrm += x[i] * x[i];
            float inv = 1.0f / (nrm + 1.0f);
            float xn[9];
#pragma unroll
            for (int i = 0; i < 9; i++) xn[i] = x[i] * inv;
            float* op = g_Xn + ((size_t)n * CC + c) * 9;
#pragma unroll
            for (int i = 0; i < 9; i++) op[i] = xn[i];
            float ic = (xn[0] + xn[4] + xn[8]) * (1.0f / 3.0f);
            int o = ni * 64 + c;
            sc[0 * PL + o] = ic;
            sc[1 * PL + o] = 0.5f * (xn[1] - xn[3]);
            sc[2 * PL + o] = 0.5f * (xn[2] - xn[6]);
            sc[3 * PL + o] = 0.5f * (xn[5] - xn[7]);
            sc[4 * PL + o] = xn[0] - ic;
            sc[5 * PL + o] = 0.5f * (xn[1] + xn[3]);
            sc[6 * PL + o] = 0.5f * (xn[2] + xn[6]);
            sc[7 * PL + o] = xn[4] - ic;
            sc[8 * PL + o] = 0.5f * (xn[5] + xn[7]);
            sc[9 * PL + o] = xn[8] - ic;
        }
    }
    __syncthreads();

    {
        int ni = tid >> 5, g = tid & 31;
        int j0 = g * 2;
        int n = n0 + ni;
        if (n >= NN) return;
        float aI[2] = {0, 0};
        float aA[3][2] = {};
        float aS[6][2] = {};
        const float* scb = sc + ni * 64;
#pragma unroll 4
        for (int k = 0; k < 64; k++) {
            float c10[10];
#pragma unroll
            for (int q = 0; q < 10; q++) c10[q] = scb[q * PL + k];
            float2 w0 = *(const float2*)&sW[k * 64 + j0];
            float2 w1 = *(const float2*)&sW[4096 + k * 64 + j0];
            float2 w2 = *(const float2*)&sW[8192 + k * 64 + j0];
            aI[0] += c10[0] * w0.x; aI[1] += c10[0] * w0.y;
#pragma unroll
            for (int i = 0; i < 3; i++) { aA[i][0] += c10[1 + i] * w1.x; aA[i][1] += c10[1 + i] * w1.y; }
#pragma unroll
            for (int i = 0; i < 6; i++) { aS[i][0] += c10[4 + i] * w2.x; aS[i][1] += c10[4 + i] * w2.y; }
        }
#pragma unroll
        for (int j = 0; j < 2; j++) {
            int l = j0 + j;
            float4* q = reinterpret_cast<float4*>(g_comp + ((size_t)n * 64 + l) * 12);
            q[0] = make_float4(aI[j], aA[0][j], aA[1][j], aA[2][j]);
            q[1] = make_float4(aS[0][j], aS[1][j], aS[2][j], aS[3][j]);
            q[2] = make_float4(aS[4][j], aS[5][j], 0.f, 0.f);
        }
    }
}

// ---------------------------------------------------------------- MLP kernel
// Persistent, 512 threads. 64-edge tiles; 3-layer MLP (FFMA2); writes f = silu*cw.
__global__ void __launch_bounds__(512, 1) k_mlp(
    const float* __restrict__ edge_attr, const float* __restrict__ edge_weight,
    const float* __restrict__ W1, const float* __restrict__ b1,
    const float* __restrict__ W2, const float* __restrict__ b2,
    const float* __restrict__ W3, const float* __restrict__ b3) {
    extern __shared__ float sm[];
    float* sW1 = sm;               // 2048
    float* sW2 = sW1 + 2048;       // 8192
    float* sW3 = sW2 + 8192;       // 24576
    float* sB1 = sW3 + 24576;      // 64
    float* sB2 = sB1 + 64;         // 128
    float* sB3 = sB2 + 128;        // 192
    float* sAt = sB3 + 192;        // 2048
    float* sH1 = sAt + 2048;       // 4096
    float* sH2 = sH1 + 4096;       // 8192
    float* sCw = sH2 + 8192;       // 64

    int tid = threadIdx.x;
    for (int i = tid; i < 2048; i += 512) sW1[i] = W1[i];
    for (int i = tid; i < 8192; i += 512) sW2[i] = W2[i];
    for (int i = tid; i < 24576; i += 512) sW3[i] = W3[i];
    if (tid < 64) sB1[tid] = b1[tid];
    else if (tid < 192) sB2[tid - 64] = b2[tid - 64];
    else if (tid < 384) sB3[tid - 192] = b3[tid - 192];
    __syncthreads();

    const int tx = tid & 15, ty = tid >> 4;   // ty in [0,32)
    const int e0 = tx * 4;
    const int nTiles = EE / 64;

    for (int tile = blockIdx.x; tile < nTiles; tile += gridDim.x) {
        int base = tile * 64;
        if (tid < 64) {
            float w = edge_weight[base + tid];
            float cw = 0.5f * (__cosf(w * PI_OVER_CUT) + 1.0f);
            sCw[tid] = (w < CUTOFF_F) ? cw : 0.0f;
        }
        {
            int e = tid >> 3, kq = tid & 7;
            float4 v = __ldg(reinterpret_cast<const float4*>(edge_attr + ((size_t)(base + e)) * 32 + kq * 4));
            sAt[(kq * 4 + 0) * 64 + e] = v.x;
            sAt[(kq * 4 + 1) * 64 + e] = v.y;
            sAt[(kq * 4 + 2) * 64 + e] = v.z;
            sAt[(kq * 4 + 3) * 64 + e] = v.w;
        }
        __syncthreads();

        // ---- layer 1
        {
            int j0 = ty * 2;
            ull acc[4];
            {
                ull b = lds64(&sB1[j0]);
#pragma unroll
                for (int ee = 0; ee < 4; ee++) acc[ee] = b;
            }
#pragma unroll 4
            for (int k = 0; k < 32; k++) {
                float4 av = *(const float4*)&sAt[k * 64 + e0];
                ull w = lds64(&sW1[k * 64 + j0]);
                ffma2(acc[0], pack2(av.x), w);
                ffma2(acc[1], pack2(av.y), w);
                ffma2(acc[2], pack2(av.z), w);
                ffma2(acc[3], pack2(av.w), w);
            }
            float2 u[4];
#pragma unroll
            for (int ee = 0; ee < 4; ee++) u[ee] = unp2(acc[ee]);
            *(float4*)&sH1[j0 * 64 + e0] =
                make_float4(silu_f(u[0].x), silu_f(u[1].x), silu_f(u[2].x), silu_f(u[3].x));
            *(float4*)&sH1[(j0 + 1) * 64 + e0] =
                make_float4(silu_f(u[0].y), silu_f(u[1].y), silu_f(u[2].y), silu_f(u[3].y));
        }
        __syncthreads();

        // ---- layer 2
        {
            int j0 = ty * 4;
            ull acc[4][2];
            {
                ulonglong2 b = *(const ulonglong2*)&sB2[j0];
#pragma unroll
                for (int ee = 0; ee < 4; ee++) { acc[ee][0] = b.x; acc[ee][1] = b.y; }
            }
#pragma unroll 4
            for (int k = 0; k < 64; k++) {
                float4 av = *(const float4*)&sH1[k * 64 + e0];
                ulonglong2 w = *(const ulonglong2*)&sW2[k * 128 + j0];
                ull a2[4] = {pack2(av.x), pack2(av.y), pack2(av.z), pack2(av.w)};
#pragma unroll
                for (int ee = 0; ee < 4; ee++) { ffma2(acc[ee][0], a2[ee], w.x); ffma2(acc[ee][1], a2[ee], w.y); }
            }
#pragma unroll
            for (int q = 0; q < 2; q++) {
                float2 u[4];
#pragma unroll
                for (int ee = 0; ee < 4; ee++) u[ee] = unp2(acc[ee][q]);
                *(float4*)&sH2[(j0 + 2 * q) * 64 + e0] =
                    make_float4(silu_f(u[0].x), silu_f(u[1].x), silu_f(u[2].x), silu_f(u[3].x));
                *(float4*)&sH2[(j0 + 2 * q + 1) * 64 + e0] =
                    make_float4(silu_f(u[0].y), silu_f(u[1].y), silu_f(u[2].y), silu_f(u[3].y));
            }
        }
        __syncthreads();

        // ---- layer 3 + write f
        {
            int j0 = ty * 6;
            ull acc[4][3];
            {
                ull b0 = lds64(&sB3[j0]), b1v = lds64(&sB3[j0 + 2]), b2v = lds64(&sB3[j0 + 4]);
#pragma unroll
                for (int ee = 0; ee < 4; ee++) { acc[ee][0] = b0; acc[ee][1] = b1v; acc[ee][2] = b2v; }
            }
#pragma unroll 4
            for (int k = 0; k < 128; k++) {
                float4 av = *(const float4*)&sH2[k * 64 + e0];
                ull w0 = lds64(&sW3[k * 192 + j0]);
                ull w1 = lds64(&sW3[k * 192 + j0 + 2]);
                ull w2 = lds64(&sW3[k * 192 + j0 + 4]);
                ull a2[4] = {pack2(av.x), pack2(av.y), pack2(av.z), pack2(av.w)};
#pragma unroll
                for (int ee = 0; ee < 4; ee++) {
                    ffma2(acc[ee][0], a2[ee], w0);
                    ffma2(acc[ee][1], a2[ee], w1);
                    ffma2(acc[ee][2], a2[ee], w2);
                }
            }
#pragma unroll
            for (int ee = 0; ee < 4; ee++) {
                int e = e0 + ee;
                float cw = sCw[e];
                float2 u0 = unp2(acc[ee][0]), u1 = unp2(acc[ee][1]), u2 = unp2(acc[ee][2]);
                float2* fp = reinterpret_cast<float2*>(g_f + (size_t)(base + e) * 192 + j0);
                fp[0] = make_float2(silu_f(u0.x) * cw, silu_f(u0.y) * cw);
                fp[1] = make_float2(silu_f(u1.x) * cw, silu_f(u1.y) * cw);
                fp[2] = make_float2(silu_f(u2.x) * cw, silu_f(u2.y) * cw);
            }
        }
        __syncthreads();
    }
}

// ---------------------------------------------------------------- gather (pull)
// One warp per src node; lane owns 2 channels; no atomics.
__global__ void __launch_bounds__(256) k_gather() {
    int warp = (blockIdx.x * blockDim.x + threadIdx.x) >> 5;
    if (warp >= NN) return;
    int lane = threadIdx.x & 31;
    int n = warp;
    int off = g_off[n], deg = g_deg[n];
    const int c0 = lane * 2;

    float acc[24];
#pragma unroll
    for (int i = 0; i < 24; i++) acc[i] = 0.f;

    for (int k = 0; k < deg; k++) {
        int eid = g_eid[off + k];
        int d = g_cdst[off + k];
        const float* fp = g_f + (size_t)eid * 192 + c0 * 3;
        float2 fa = *(const float2*)(fp);
        float2 fb = *(const float2*)(fp + 2);
        float2 fc = *(const float2*)(fp + 4);
        // channel c0: fI=fa.x fA=fa.y fS=fb.x ; channel c0+1: fI=fb.y fA=fc.x fS=fc.y
        const float4* p0 = reinterpret_cast<const float4*>(g_comp + ((size_t)d * 64 + c0) * 12);
        float4 v0 = __ldg(p0), v1 = __ldg(p0 + 1), v2 = __ldg(p0 + 2);
        acc[0] += fa.x * v0.x;
        acc[1] += fa.y * v0.y;  acc[2] += fa.y * v0.z;  acc[3] += fa.y * v0.w;
        acc[4] += fb.x * v1.x;  acc[5] += fb.x * v1.y;  acc[6] += fb.x * v1.z;
        acc[7] += fb.x * v1.w;  acc[8] += fb.x * v2.x;  acc[9] += fb.x * v2.y;
        const float4* p1 = reinterpret_cast<const float4*>(g_comp + ((size_t)d * 64 + c0 + 1) * 12);
        float4 w0 = __ldg(p1), w1 = __ldg(p1 + 1), w2 = __ldg(p1 + 2);
        acc[12] += fb.y * w0.x;
        acc[13] += fc.x * w0.y; acc[14] += fc.x * w0.z; acc[15] += fc.x * w0.w;
        acc[16] += fc.y * w1.x; acc[17] += fc.y * w1.y; acc[18] += fc.y * w1.z;
        acc[19] += fc.y * w1.w; acc[20] += fc.y * w2.x; acc[21] += fc.y * w2.y;
    }
    acc[10] = acc[11] = acc[22] = acc[23] = 0.f;

    float4* q0 = reinterpret_cast<float4*>(g_msg + ((size_t)n * 64 + c0) * 12);
    q0[0] = make_float4(acc[0], acc[1], acc[2], acc[3]);
    q0[1] = make_float4(acc[4], acc[5], acc[6], acc[7]);
    q0[2] = make_float4(acc[8], acc[9], 0.f, 0.f);
    float4* q1 = reinterpret_cast<float4*>(g_msg + ((size_t)n * 64 + c0 + 1) * 12);
    q1[0] = make_float4(acc[12], acc[13], acc[14], acc[15]);
    q1[1] = make_float4(acc[16], acc[17], acc[18], acc[19]);
    q1[2] = make_float4(acc[20], acc[21], 0.f, 0.f);
}

// ---------------------------------------------------------------- node post
__global__ void __launch_bounds__(256) k_node_post(const float* __restrict__ Wt,
                                                   float* __restrict__ out) {
    extern __shared__ float sm[];
    float* sW = sm;              // 3*4096 (Wt3, Wt4, Wt5)
    float* sc = sW + 3 * 4096;   // 10 * NPB*64 (planar)

    const int PL = NPB * 64;
    int tid = threadIdx.x;
    for (int i = tid; i < 3 * 4096; i += 256) sW[i] = Wt[3 * 4096 + i];

    int n0 = blockIdx.x * NPB;

    for (int idx = tid; idx < NPB * CC; idx += 256) {
        int ni = idx >> 6, c = idx & 63;
        int n = n0 + ni;
        if (n < NN) {
            const float4* mp = reinterpret_cast<const float4*>(g_msg + ((size_t)n * 64 + c) * 12);
            float4 m0 = mp[0], m1 = mp[1], m2 = mp[2];
            const float4* yp = reinterpret_cast<const float4*>(g_comp + ((size_t)n * 64 + c) * 12);
            float4 y0 = yp[0], y1 = yp[1], y2 = yp[2];
            float Mg[3][3], Y[3][3];
            build_mat(Mg, m0.x, m0.y, m0.z, m0.w, m1.x, m1.y, m1.z, m1.w, m2.x, m2.y);
            build_mat(Y, y0.x, y0.y, y0.z, y0.w, y1.x, y1.y, y1.z, y1.w, y2.x, y2.y);
            float P[3][3];
#pragma unroll
            for (int i = 0; i < 3; i++)
#pragma unroll
                for (int j = 0; j < 3; j++) {
                    float v = 0.f;
#pragma unroll
                    for (int k = 0; k < 3; k++) v += Mg[i][k] * Y[k][j] + Y[i][k] * Mg[k][j];
                    P[i][j] = v;
                }
            float nrm = 0.f;
#pragma unroll
            for (int i = 0; i < 3; i++)
#pragma unroll
                for (int j = 0; j < 3; j++) nrm += P[i][j] * P[i][j];
            float inv = 1.0f / (nrm + 1.0f);
            float ic = (P[0][0] + P[1][1] + P[2][2]) * (1.0f / 3.0f);
            int o = ni * 64 + c;
            sc[0 * PL + o] = ic * inv;
            sc[1 * PL + o] = 0.5f * (P[0][1] - P[1][0]) * inv;
            sc[2 * PL + o] = 0.5f * (P[0][2] - P[2][0]) * inv;
            sc[3 * PL + o] = 0.5f * (P[1][2] - P[2][1]) * inv;
            sc[4 * PL + o] = (P[0][0] - ic) * inv;
            sc[5 * PL + o] = 0.5f * (P[0][1] + P[1][0]) * inv;
            sc[6 * PL + o] = 0.5f * (P[0][2] + P[2][0]) * inv;
            sc[7 * PL + o] = (P[1][1] - ic) * inv;
            sc[8 * PL + o] = 0.5f * (P[1][2] + P[2][1]) * inv;
            sc[9 * PL + o] = (P[2][2] - ic) * inv;
        }
    }
    __syncthreads();

    {
        int ni = tid >> 5, g = tid & 31;
        int j0 = g * 2;
        int n = n0 + ni;
        if (n >= NN) return;
        float aI[2] = {0, 0};
        float aA[3][2] = {};
        float aS[6][2] = {};
        const float* scb = sc + ni * 64;
#pragma unroll 4
        for (int k = 0; k < 64; k++) {
            float c10[10];
#pragma unroll
            for (int q = 0; q < 10; q++) c10[q] = scb[q * PL + k];
            float2 w0 = *(const float2*)&sW[k * 64 + j0];
            float2 w1 = *(const float2*)&sW[4096 + k * 64 + j0];
            float2 w2 = *(const float2*)&sW[8192 + k * 64 + j0];
            aI[0] += c10[0] * w0.x; aI[1] += c10[0] * w0.y;
#pragma unroll
            for (int i = 0; i < 3; i++) { aA[i][0] += c10[1 + i] * w1.x; aA[i][1] += c10[1 + i] * w1.y; }
#pragma unroll
            for (int i = 0; i < 6; i++) { aS[i][0] += c10[4 + i] * w2.x; aS[i][1] += c10[4 + i] * w2.y; }
        }
#pragma unroll
        for (int j = 0; j < 2; j++) {
            int l = j0 + j;
            float D[3][3];
            build_mat(D, aI[j], aA[0][j], aA[1][j], aA[2][j],
                      aS[0][j], aS[1][j], aS[2][j], aS[3][j], aS[4][j], aS[5][j]);
            const float* xp = g_Xn + ((size_t)n * 64 + l) * 9;
            float* op = out + ((size_t)n * 64 + l) * 9;
#pragma unroll
            for (int i = 0; i < 3; i++)
#pragma unroll
                for (int j2 = 0; j2 < 3; j2++) {
                    float dd = 0.f;
#pragma unroll
                    for (int k = 0; k < 3; k++) dd += D[i][k] * D[k][j2];
                    op[i * 3 + j2] = __ldg(xp + i * 3 + j2) + D[i][j2] + dd;
                }
        }
    }
}

// ---------------------------------------------------------------- launch
extern "C" void kernel_launch(void* const* d_in, const int* in_sizes, int n_in,
                              void* d_out, int out_size) {
    const float* X  = (const float*)d_in[0];
    const int*   ei = (const int*)d_in[1];
    const float* ew = (const float*)d_in[2];
    const float* ea = (const float*)d_in[3];
    const float* W1 = (const float*)d_in[4];
    const float* b1 = (const float*)d_in[5];
    const float* W2 = (const float*)d_in[6];
    const float* b2 = (const float*)d_in[7];
    const float* W3 = (const float*)d_in[8];
    const float* b3 = (const float*)d_in[9];
    const float* Wt = (const float*)d_in[10];
    float* out = (float*)d_out;

    const int smNode = (3 * 4096 + NPB * 64 * 10) * 4;   // ~68 KB
    const int smMlp = (2048 + 8192 + 24576 + 64 + 128 + 192 + 2048 +
                       4096 + 8192 + 64) * 4;             // ~194 KB

    cudaFuncSetAttribute(k_node_pre, cudaFuncAttributeMaxDynamicSharedMemorySize, smNode);
    cudaFuncSetAttribute(k_node_post, cudaFuncAttributeMaxDynamicSharedMemorySize, smNode);
    cudaFuncSetAttribute(k_mlp, cudaFuncAttributeMaxDynamicSharedMemorySize, smMlp);

    k_zero_deg<<<(NN + 255) / 256, 256>>>();
    k_hist<<<(EE + 255) / 256, 256>>>(ei);
    k_scan<<<1, 1024>>>();
    k_fill<<<(EE + 255) / 256, 256>>>(ei);
    k_node_pre<<<(NN + NPB - 1) / NPB, 256, smNode>>>(X, Wt);
    k_mlp<<<148, 512, smMlp>>>(ea, ew, W1, b1, W2, b2, W3, b3);
    k_gather<<<(NN * 32 + 255) / 256, 256>>>();
    k_node_post<<<(NN + NPB - 1) / NPB, 256, smNode>>>(Wt, out);
}